// round 4
// baseline (speedup 1.0000x reference)
#include <cuda_runtime.h>
#include <cstdint>

#define LL 2
#define BB 32
#define SS 2048
#define HH 512
#define DD 1024   // D = 2*H

#define SSPLIT 8

// Scratch (no cudaMalloc allowed)
__device__ float g_ehb[BB * HH];
__device__ float g_scores[BB * SS];
__device__ float g_ctx[SSPLIT][BB][DD];

__device__ __forceinline__ uint32_t f2tf32(float x) {
    uint32_t r;
    asm("cvt.rna.tf32.f32 %0, %1;" : "=r"(r) : "f"(x));
    return r;
}

// ---------------------------------------------------------------------------
// Kernel 1: ehb[b][h] = sum_d hidden[-1][b][d] * w_h[h][d] + attn_b[h]
// ---------------------------------------------------------------------------
__global__ void ehb_kernel(const float* __restrict__ hidden,
                           const float* __restrict__ attn_w,
                           const float* __restrict__ attn_b) {
    int warp = threadIdx.x >> 5;
    int lane = threadIdx.x & 31;
    int h = blockIdx.x * 4 + warp;
    int b = blockIdx.y;
    const float* hid = hidden + (size_t)(LL - 1) * BB * DD + (size_t)b * DD;
    const float* w   = attn_w + (size_t)h * (2 * DD);
    float acc = 0.f;
    #pragma unroll 8
    for (int d = lane; d < DD; d += 32) acc += hid[d] * w[d];
    #pragma unroll
    for (int o = 16; o > 0; o >>= 1) acc += __shfl_xor_sync(0xffffffffu, acc, o);
    if (lane == 0) g_ehb[b * HH + h] = acc + attn_b[h];
}

// ---------------------------------------------------------------------------
// Kernel 2: scores[b][s] = sum_h v[h] * tanh(e_e[b][s][h] + ehb[b][h])
// TF32 mma.sync GEMM, BM=128, BN=128 (x4 chunks over H), BK=16,
// double-buffered smem, 1 syncthreads per k-step.
// 8 warps: 4(m) x 2(n), warp tile 32 x 64.
// ---------------------------------------------------------------------------
#define BM 128
#define BN 128
#define BK 16
#define NCHUNK (HH / BN)   // 4

__global__ __launch_bounds__(256) void scores_kernel(
    const float* __restrict__ enc,
    const float* __restrict__ attn_w,
    const float* __restrict__ v_w)
{
    __shared__ uint32_t As[2][BK][BM + 4];
    __shared__ uint32_t Bs[2][BK][BN + 4];
    __shared__ float s_score[BM];

    const int b   = blockIdx.y;
    const int s0  = blockIdx.x * BM;
    const int tid = threadIdx.x;
    const int warp = tid >> 5, lane = tid & 31;
    const int wm = warp >> 1, wn = warp & 1;   // 4 x 2 warp grid
    const int g  = lane >> 2, tg = lane & 3;

    for (int i = tid; i < BM; i += 256) s_score[i] = 0.f;
    __syncthreads();

    const float* encb = enc + ((size_t)b * SS + s0) * DD;
    const float* we   = attn_w + DD;           // w_e[h][d] = attn_w[h*2D + D + d]
    const float* ehb  = g_ehb + b * HH;

    float p[4] = {0.f, 0.f, 0.f, 0.f};

    // loaders: 128 rows x 16 k, 2 float4 per thread (both A and B tiles)
    const int lr = tid >> 1;             // row 0..127
    const int lq = (tid & 1) * 2;        // quad base 0 or 2

    for (int nc = 0; nc < NCHUNK; nc++) {
        const int h0 = nc * BN;
        float acc[2][8][4];
        #pragma unroll
        for (int f = 0; f < 2; f++)
            #pragma unroll
            for (int j = 0; j < 8; j++)
                #pragma unroll
                for (int r = 0; r < 4; r++) acc[f][j][r] = 0.f;

        const float* arow = encb + (size_t)lr * DD;
        const float* brow = we + (size_t)(h0 + lr) * (2 * DD);

        float4 ra[2], rb[2];
        // prologue: k0 = 0
        #pragma unroll
        for (int q = 0; q < 2; q++) {
            ra[q] = *(const float4*)(arow + (lq + q) * 4);
            rb[q] = *(const float4*)(brow + (lq + q) * 4);
        }
        #pragma unroll
        for (int q = 0; q < 2; q++) {
            int kq = lq + q;
            As[0][kq * 4 + 0][lr] = f2tf32(ra[q].x);
            As[0][kq * 4 + 1][lr] = f2tf32(ra[q].y);
            As[0][kq * 4 + 2][lr] = f2tf32(ra[q].z);
            As[0][kq * 4 + 3][lr] = f2tf32(ra[q].w);
            Bs[0][kq * 4 + 0][lr] = f2tf32(rb[q].x);
            Bs[0][kq * 4 + 1][lr] = f2tf32(rb[q].y);
            Bs[0][kq * 4 + 2][lr] = f2tf32(rb[q].z);
            Bs[0][kq * 4 + 3][lr] = f2tf32(rb[q].w);
        }
        __syncthreads();

        int buf = 0;
        for (int k0 = 0; k0 < DD; k0 += BK) {
            const bool haveNext = (k0 + BK < DD);
            if (haveNext) {
                #pragma unroll
                for (int q = 0; q < 2; q++) {
                    ra[q] = *(const float4*)(arow + k0 + BK + (lq + q) * 4);
                    rb[q] = *(const float4*)(brow + k0 + BK + (lq + q) * 4);
                }
            }

            #pragma unroll
            for (int kk = 0; kk < BK; kk += 8) {
                uint32_t a[2][4], bfr[8][2];
                #pragma unroll
                for (int f = 0; f < 2; f++) {
                    int rm = wm * 32 + f * 16;
                    a[f][0] = As[buf][kk + tg    ][rm + g    ];
                    a[f][1] = As[buf][kk + tg    ][rm + g + 8];
                    a[f][2] = As[buf][kk + tg + 4][rm + g    ];
                    a[f][3] = As[buf][kk + tg + 4][rm + g + 8];
                }
                #pragma unroll
                for (int j = 0; j < 8; j++) {
                    int cb = wn * 64 + j * 8;
                    bfr[j][0] = Bs[buf][kk + tg    ][cb + g];
                    bfr[j][1] = Bs[buf][kk + tg + 4][cb + g];
                }
                #pragma unroll
                for (int f = 0; f < 2; f++)
                    #pragma unroll
                    for (int j = 0; j < 8; j++)
                        asm volatile(
                            "mma.sync.aligned.m16n8k8.row.col.f32.tf32.tf32.f32 "
                            "{%0,%1,%2,%3}, {%4,%5,%6,%7}, {%8,%9}, {%0,%1,%2,%3};"
                            : "+f"(acc[f][j][0]), "+f"(acc[f][j][1]),
                              "+f"(acc[f][j][2]), "+f"(acc[f][j][3])
                            : "r"(a[f][0]), "r"(a[f][1]), "r"(a[f][2]), "r"(a[f][3]),
                              "r"(bfr[j][0]), "r"(bfr[j][1]));
            }

            if (haveNext) {
                int nb = buf ^ 1;
                #pragma unroll
                for (int q = 0; q < 2; q++) {
                    int kq = lq + q;
                    As[nb][kq * 4 + 0][lr] = f2tf32(ra[q].x);
                    As[nb][kq * 4 + 1][lr] = f2tf32(ra[q].y);
                    As[nb][kq * 4 + 2][lr] = f2tf32(ra[q].z);
                    As[nb][kq * 4 + 3][lr] = f2tf32(ra[q].w);
                    Bs[nb][kq * 4 + 0][lr] = f2tf32(rb[q].x);
                    Bs[nb][kq * 4 + 1][lr] = f2tf32(rb[q].y);
                    Bs[nb][kq * 4 + 2][lr] = f2tf32(rb[q].z);
                    Bs[nb][kq * 4 + 3][lr] = f2tf32(rb[q].w);
                }
            }
            __syncthreads();
            buf ^= 1;
        }

        // epilogue: tanh(acc + ehb[h]) * v[h]
        #pragma unroll
        for (int j = 0; j < 8; j++) {
            #pragma unroll
            for (int half = 0; half < 2; half++) {
                int h = h0 + wn * 64 + j * 8 + 2 * tg + half;
                float eh = ehb[h];
                float vv = v_w[h];
                #pragma unroll
                for (int f = 0; f < 2; f++) {
                    p[f * 2 + 0] += tanhf(acc[f][j][half]     + eh) * vv;
                    p[f * 2 + 1] += tanhf(acc[f][j][2 + half] + eh) * vv;
                }
            }
        }
    }

    // reduce over quad (cols) then across wn via smem atomics
    #pragma unroll
    for (int i = 0; i < 4; i++) {
        p[i] += __shfl_xor_sync(0xffffffffu, p[i], 1);
        p[i] += __shfl_xor_sync(0xffffffffu, p[i], 2);
    }
    if (tg == 0) {
        #pragma unroll
        for (int i = 0; i < 4; i++) {
            int row = wm * 32 + (i >> 1) * 16 + g + (i & 1) * 8;
            atomicAdd(&s_score[row], p[i]);
        }
    }
    __syncthreads();
    if (tid < BM) g_scores[b * SS + s0 + tid] = s_score[tid];
}

// ---------------------------------------------------------------------------
// Kernel 3: softmax over S per batch; writes attention weights
// ---------------------------------------------------------------------------
__global__ __launch_bounds__(256) void softmax_kernel(float* __restrict__ out) {
    __shared__ float sh[SS];
    __shared__ float red[256];
    const int b = blockIdx.x;
    const int tid = threadIdx.x;

    float m = -1e30f;
    for (int s = tid; s < SS; s += 256) {
        float v = g_scores[b * SS + s];
        sh[s] = v;
        m = fmaxf(m, v);
    }
    red[tid] = m;
    __syncthreads();
    for (int o = 128; o > 0; o >>= 1) {
        if (tid < o) red[tid] = fmaxf(red[tid], red[tid + o]);
        __syncthreads();
    }
    const float mx = red[0];
    __syncthreads();

    float sum = 0.f;
    for (int s = tid; s < SS; s += 256) {
        float e = expf(sh[s] - mx);
        sh[s] = e;
        sum += e;
    }
    red[tid] = sum;
    __syncthreads();
    for (int o = 128; o > 0; o >>= 1) {
        if (tid < o) red[tid] += red[tid + o];
        __syncthreads();
    }
    const float inv = 1.f / red[0];
    __syncthreads();

    float* wout = out + BB * DD + (size_t)b * SS;
    for (int s = tid; s < SS; s += 256) wout[s] = sh[s] * inv;
}

// ---------------------------------------------------------------------------
// Kernel 4a: partial context over an S chunk. grid (D/256, B, SSPLIT).
// ---------------------------------------------------------------------------
__global__ __launch_bounds__(256) void context_part_kernel(
    const float* __restrict__ enc,
    const float* __restrict__ weights)
{
    __shared__ float w[SS / SSPLIT];
    const int b = blockIdx.y;
    const int sc = blockIdx.z;
    const int sbase = sc * (SS / SSPLIT);
    const int d = blockIdx.x * 256 + threadIdx.x;
    for (int s = threadIdx.x; s < SS / SSPLIT; s += 256)
        w[s] = weights[(size_t)b * SS + sbase + s];
    __syncthreads();

    const float* e = enc + ((size_t)b * SS + sbase) * DD + d;
    float acc = 0.f;
    #pragma unroll 8
    for (int s = 0; s < SS / SSPLIT; s++) acc += w[s] * e[(size_t)s * DD];
    g_ctx[sc][b][d] = acc;
}

// Kernel 4b: reduce partials. grid (B*D/256), 256 threads.
__global__ __launch_bounds__(256) void context_reduce_kernel(float* __restrict__ out) {
    const int idx = blockIdx.x * 256 + threadIdx.x;
    const int b = idx / DD, d = idx % DD;
    float acc = 0.f;
    #pragma unroll
    for (int p = 0; p < SSPLIT; p++) acc += g_ctx[p][b][d];
    out[idx] = acc;
}

// ---------------------------------------------------------------------------
extern "C" void kernel_launch(void* const* d_in, const int* in_sizes, int n_in,
                              void* d_out, int out_size) {
    const float* hidden = (const float*)d_in[0];
    const float* enc    = (const float*)d_in[1];
    const float* attn_w = (const float*)d_in[2];
    const float* attn_b = (const float*)d_in[3];
    const float* v_w    = (const float*)d_in[4];
    float* out = (float*)d_out;

    ehb_kernel<<<dim3(HH / 4, BB), 128>>>(hidden, attn_w, attn_b);
    scores_kernel<<<dim3(SS / BM, BB), 256>>>(enc, attn_w, v_w);
    softmax_kernel<<<BB, 256>>>(out);
    context_part_kernel<<<dim3(DD / 256, BB, SSPLIT), 256>>>(enc, out + BB * DD);
    context_reduce_kernel<<<(BB * DD) / 256, 256>>>(out);
}

// round 5
// speedup vs baseline: 3.2243x; 3.2243x over previous
#include <cuda_runtime.h>
#include <cstdint>

#define LL 2
#define BB 32
#define SS 2048
#define HH 512
#define DD 1024   // D = 2*H

#define SSPLIT 8

#define BM 128
#define BN 128
#define BK 32
#define NK (DD / BK)       // 32 k-steps
#define NCHUNK (HH / BN)   // 4 h-chunks (grid dim)
#define STAGES 3
#define AKS 36             // smem row stride (floats): 32 + 4 pad, conflict-free
#define TILE_FLTS (128 * AKS)

// Scratch (no cudaMalloc allowed)
__device__ float g_ehb[BB * HH];
__device__ float g_spart[NCHUNK][BB][SS];
__device__ float g_ctx[SSPLIT][BB][DD];

#define CP16(dst_u32, src_ptr) \
    asm volatile("cp.async.cg.shared.global [%0], [%1], 16;" :: "r"(dst_u32), "l"(src_ptr))
#define CP_COMMIT() asm volatile("cp.async.commit_group;" ::: "memory")
#define CP_WAIT1()  asm volatile("cp.async.wait_group 1;" ::: "memory")

// ---------------------------------------------------------------------------
// Kernel 1: ehb[b][h] = sum_d hidden[-1][b][d] * w_h[h][d] + attn_b[h]
// ---------------------------------------------------------------------------
__global__ void ehb_kernel(const float* __restrict__ hidden,
                           const float* __restrict__ attn_w,
                           const float* __restrict__ attn_b) {
    int warp = threadIdx.x >> 5;
    int lane = threadIdx.x & 31;
    int h = blockIdx.x * 4 + warp;
    int b = blockIdx.y;
    const float* hid = hidden + (size_t)(LL - 1) * BB * DD + (size_t)b * DD;
    const float* w   = attn_w + (size_t)h * (2 * DD);
    float acc = 0.f;
    #pragma unroll 8
    for (int d = lane; d < DD; d += 32) acc += hid[d] * w[d];
    #pragma unroll
    for (int o = 16; o > 0; o >>= 1) acc += __shfl_xor_sync(0xffffffffu, acc, o);
    if (lane == 0) g_ehb[b * HH + h] = acc + attn_b[h];
}

// ---------------------------------------------------------------------------
// Kernel 2: partial scores. grid (NCHUNK, S/BM, B), 512 threads.
// spart[nc][b][s] = sum_{h in chunk nc} v[h] * tanh(e_e[b][s][h] + ehb[b][h])
// TF32 mma.sync, 3-stage cp.async pipeline, BM=128 BN=128 BK=32.
// 16 warps: 4(m) x 4(n), warp tile 32 x 32 (32 acc regs — no spill).
// ---------------------------------------------------------------------------
__global__ __launch_bounds__(512) void scores_part_kernel(
    const float* __restrict__ enc,
    const float* __restrict__ attn_w,
    const float* __restrict__ v_w)
{
    extern __shared__ float smem[];
    float* As   = smem;                       // [STAGES][128][AKS]
    float* Bs   = smem + STAGES * TILE_FLTS;  // [STAGES][128][AKS]
    float* s_sc = smem + 2 * STAGES * TILE_FLTS; // [4][128]

    const int nc    = blockIdx.x;
    const int s0    = blockIdx.y * BM;
    const int b     = blockIdx.z;
    const int h0    = nc * BN;
    const int tid   = threadIdx.x;
    const int warp  = tid >> 5, lane = tid & 31;
    const int wm    = warp >> 2, wn = warp & 3;   // 4 x 4 warp grid
    const int g     = lane >> 2, tg = lane & 3;

    // loaders: 128 rows, 8 x 16B segments per row; 4 threads/row, 2 segs each
    const int lrow  = tid >> 2;
    const int lseg2 = (tid & 3) * 2;

    const float* aptr = enc + ((size_t)b * SS + s0 + lrow) * DD + lseg2 * 4;
    const float* bptr = attn_w + DD + (size_t)(h0 + lrow) * (2 * DD) + lseg2 * 4;

    uint32_t sA, sB;
    {
        uint64_t a64 = __cvta_generic_to_shared(As);
        uint64_t b64 = __cvta_generic_to_shared(Bs);
        sA = (uint32_t)a64;
        sB = (uint32_t)b64;
    }

    float acc[2][4][4];
    #pragma unroll
    for (int f = 0; f < 2; f++)
        #pragma unroll
        for (int j = 0; j < 4; j++)
            #pragma unroll
            for (int r = 0; r < 4; r++) acc[f][j][r] = 0.f;

    // prologue: stages 0, 1
    #pragma unroll
    for (int s = 0; s < 2; s++) {
        #pragma unroll
        for (int q = 0; q < 2; q++) {
            uint32_t off = (uint32_t)((s * TILE_FLTS + lrow * AKS + (lseg2 + q) * 4) * 4);
            CP16(sA + off, aptr + s * BK + q * 4);
            CP16(sB + off, bptr + s * BK + q * 4);
        }
        CP_COMMIT();
    }

    for (int i = 0; i < NK; i++) {
        CP_WAIT1();
        __syncthreads();

        // prefetch stage i+2
        if (i + 2 < NK) {
            int st = (i + 2) % STAGES;
            #pragma unroll
            for (int q = 0; q < 2; q++) {
                uint32_t off = (uint32_t)((st * TILE_FLTS + lrow * AKS + (lseg2 + q) * 4) * 4);
                CP16(sA + off, aptr + (i + 2) * BK + q * 4);
                CP16(sB + off, bptr + (i + 2) * BK + q * 4);
            }
        }
        CP_COMMIT();

        // compute stage i
        const float* At = As + (i % STAGES) * TILE_FLTS;
        const float* Bt = Bs + (i % STAGES) * TILE_FLTS;
        #pragma unroll
        for (int kk = 0; kk < 4; kk++) {
            const int k8 = kk * 8;
            uint32_t a[2][4], bf[4][2];
            #pragma unroll
            for (int f = 0; f < 2; f++) {
                int rm = wm * 32 + f * 16;
                a[f][0] = __float_as_uint(At[(rm + g    ) * AKS + k8 + tg    ]);
                a[f][1] = __float_as_uint(At[(rm + g + 8) * AKS + k8 + tg    ]);
                a[f][2] = __float_as_uint(At[(rm + g    ) * AKS + k8 + tg + 4]);
                a[f][3] = __float_as_uint(At[(rm + g + 8) * AKS + k8 + tg + 4]);
            }
            #pragma unroll
            for (int j = 0; j < 4; j++) {
                int cb = wn * 32 + j * 8;
                bf[j][0] = __float_as_uint(Bt[(cb + g) * AKS + k8 + tg    ]);
                bf[j][1] = __float_as_uint(Bt[(cb + g) * AKS + k8 + tg + 4]);
            }
            #pragma unroll
            for (int f = 0; f < 2; f++)
                #pragma unroll
                for (int j = 0; j < 4; j++)
                    asm volatile(
                        "mma.sync.aligned.m16n8k8.row.col.f32.tf32.tf32.f32 "
                        "{%0,%1,%2,%3}, {%4,%5,%6,%7}, {%8,%9}, {%0,%1,%2,%3};"
                        : "+f"(acc[f][j][0]), "+f"(acc[f][j][1]),
                          "+f"(acc[f][j][2]), "+f"(acc[f][j][3])
                        : "r"(a[f][0]), "r"(a[f][1]), "r"(a[f][2]), "r"(a[f][3]),
                          "r"(bf[j][0]), "r"(bf[j][1]));
        }
    }

    // epilogue: tanh(acc + ehb[h]) * v[h], per-thread partials over owned rows
    const float* ehb = g_ehb + b * HH;
    float p[4] = {0.f, 0.f, 0.f, 0.f};
    #pragma unroll
    for (int j = 0; j < 4; j++) {
        #pragma unroll
        for (int half = 0; half < 2; half++) {
            int h = h0 + wn * 32 + j * 8 + 2 * tg + half;
            float eh = ehb[h];
            float vv = v_w[h];
            #pragma unroll
            for (int f = 0; f < 2; f++) {
                p[f * 2 + 0] += tanhf(acc[f][j][half]     + eh) * vv;
                p[f * 2 + 1] += tanhf(acc[f][j][2 + half] + eh) * vv;
            }
        }
    }
    // reduce over quad (columns within warp)
    #pragma unroll
    for (int i = 0; i < 4; i++) {
        p[i] += __shfl_xor_sync(0xffffffffu, p[i], 1);
        p[i] += __shfl_xor_sync(0xffffffffu, p[i], 2);
    }
    __syncthreads();   // smem reuse barrier (As/Bs done)
    if (tg == 0) {
        #pragma unroll
        for (int i = 0; i < 4; i++) {
            int row = wm * 32 + (i >> 1) * 16 + g + (i & 1) * 8;
            s_sc[wn * BM + row] = p[i];
        }
    }
    __syncthreads();
    if (tid < BM) {
        float s = s_sc[0 * BM + tid] + s_sc[1 * BM + tid]
                + s_sc[2 * BM + tid] + s_sc[3 * BM + tid];
        g_spart[nc][b][s0 + tid] = s;
    }
}

// ---------------------------------------------------------------------------
// Kernel 3: softmax over S per batch (sums the NCHUNK partials, fixed order)
// ---------------------------------------------------------------------------
__global__ __launch_bounds__(256) void softmax_kernel(float* __restrict__ out) {
    __shared__ float sh[SS];
    __shared__ float red[256];
    const int b = blockIdx.x;
    const int tid = threadIdx.x;

    float m = -1e30f;
    for (int s = tid; s < SS; s += 256) {
        float v = g_spart[0][b][s];
        #pragma unroll
        for (int p = 1; p < NCHUNK; p++) v += g_spart[p][b][s];
        sh[s] = v;
        m = fmaxf(m, v);
    }
    red[tid] = m;
    __syncthreads();
    for (int o = 128; o > 0; o >>= 1) {
        if (tid < o) red[tid] = fmaxf(red[tid], red[tid + o]);
        __syncthreads();
    }
    const float mx = red[0];
    __syncthreads();

    float sum = 0.f;
    for (int s = tid; s < SS; s += 256) {
        float e = expf(sh[s] - mx);
        sh[s] = e;
        sum += e;
    }
    red[tid] = sum;
    __syncthreads();
    for (int o = 128; o > 0; o >>= 1) {
        if (tid < o) red[tid] += red[tid + o];
        __syncthreads();
    }
    const float inv = 1.f / red[0];
    __syncthreads();

    float* wout = out + BB * DD + (size_t)b * SS;
    for (int s = tid; s < SS; s += 256) wout[s] = sh[s] * inv;
}

// ---------------------------------------------------------------------------
// Kernel 4a: partial context over an S chunk. grid (D/256, B, SSPLIT).
// ---------------------------------------------------------------------------
__global__ __launch_bounds__(256) void context_part_kernel(
    const float* __restrict__ enc,
    const float* __restrict__ weights)
{
    __shared__ float w[SS / SSPLIT];
    const int b = blockIdx.y;
    const int sc = blockIdx.z;
    const int sbase = sc * (SS / SSPLIT);
    const int d = blockIdx.x * 256 + threadIdx.x;
    for (int s = threadIdx.x; s < SS / SSPLIT; s += 256)
        w[s] = weights[(size_t)b * SS + sbase + s];
    __syncthreads();

    const float* e = enc + ((size_t)b * SS + sbase) * DD + d;
    float acc = 0.f;
    #pragma unroll 8
    for (int s = 0; s < SS / SSPLIT; s++) acc += w[s] * e[(size_t)s * DD];
    g_ctx[sc][b][d] = acc;
}

// Kernel 4b: reduce partials. grid (B*D/256), 256 threads.
__global__ __launch_bounds__(256) void context_reduce_kernel(float* __restrict__ out) {
    const int idx = blockIdx.x * 256 + threadIdx.x;
    const int b = idx / DD, d = idx % DD;
    float acc = 0.f;
    #pragma unroll
    for (int p = 0; p < SSPLIT; p++) acc += g_ctx[p][b][d];
    out[idx] = acc;
}

// ---------------------------------------------------------------------------
extern "C" void kernel_launch(void* const* d_in, const int* in_sizes, int n_in,
                              void* d_out, int out_size) {
    const float* hidden = (const float*)d_in[0];
    const float* enc    = (const float*)d_in[1];
    const float* attn_w = (const float*)d_in[2];
    const float* attn_b = (const float*)d_in[3];
    const float* v_w    = (const float*)d_in[4];
    float* out = (float*)d_out;

    const int smem_bytes = (2 * STAGES * TILE_FLTS + 4 * BM) * 4;  // ~112.6 KB
    static int attr_done = 0;
    if (!attr_done) {
        cudaFuncSetAttribute(scores_part_kernel,
                             cudaFuncAttributeMaxDynamicSharedMemorySize, smem_bytes);
        attr_done = 1;
    }

    ehb_kernel<<<dim3(HH / 4, BB), 128>>>(hidden, attn_w, attn_b);
    scores_part_kernel<<<dim3(NCHUNK, SS / BM, BB), 512, smem_bytes>>>(enc, attn_w, v_w);
    softmax_kernel<<<BB, 256>>>(out);
    context_part_kernel<<<dim3(DD / 256, BB, SSPLIT), 256>>>(enc, out + BB * DD);
    context_reduce_kernel<<<(BB * DD) / 256, 256>>>(out);
}